// round 6
// baseline (speedup 1.0000x reference)
#include <cuda_runtime.h>
#include <math.h>
#include <stdint.h>

// Problem constants
#define Bn    64
#define Hn    1024
#define Tn    500
#define BHn   (Bn*Hn)
#define NGEMM 128
#define NPROJ 20
#define NCTA  148            // 1 CTA per SM
#define KCQ   16             // k per block per quarter
#define NKBQ  16             // 256 k per quarter / 16

// Per-warp smem region (floats): A[3][16*64] | Wraw[3][96*4] | Wdup[24 rows x 17 float2]
#define WSZ   5056
#define WR_O  3072
#define WD_O  4224
#define SCO   40448          // 8 * WSZ
#define SCKT  3168           // 48 * 66
#define SMF   53120          // SCO + 4*SCKT
#define SMB   (SMF*4)        // 212480 bytes

// ---------------- device scratch ----------------
__device__ float    g_Xt[(size_t)Tn * BHn];   // (T, H, B)
__device__ float    g_h0[2][BHn];             // [j][b], double buffered
__device__ float    g_h1[2][BHn];
__device__ unsigned g_cnt;
__device__ unsigned g_gen;

// ---------------- grid barrier ----------------
__device__ __forceinline__ void grid_bar() {
    __syncthreads();
    __threadfence();
    if (threadIdx.x == 0) {
        unsigned gen  = *(volatile unsigned*)&g_gen;
        unsigned prev = atomicAdd(&g_cnt, 1u);
        if (prev == NCTA - 1u) {
            atomicExch(&g_cnt, 0u);
            __threadfence();
            atomicAdd(&g_gen, 1u);
        } else {
            while (*(volatile unsigned*)&g_gen == gen) __nanosleep(64);
        }
    }
    __syncthreads();
}

// ---------------- transpose: res (B,H,T) -> g_Xt (T,H,B) ------------------
__global__ void k_transpose(const float* __restrict__ src) {
    __shared__ float tile[64][33];
    int h  = blockIdx.y;
    int t0 = blockIdx.x * 32;
    int tx = threadIdx.x, ty = threadIdx.y;   // 32 x 8
    for (int b = ty; b < 64; b += 8) {
        int t = t0 + tx;
        tile[b][tx] = (t < Tn) ? src[((size_t)b * Hn + h) * Tn + t] : 0.f;
    }
    __syncthreads();
    for (int tt = ty; tt < 32; tt += 8) {
        int t = t0 + tt;
        if (t < Tn) {
            g_Xt[(size_t)t * BHn + (size_t)h * 64 + tx]      = tile[tx][tt];
            g_Xt[(size_t)t * BHn + (size_t)h * 64 + 32 + tx] = tile[32 + tx][tt];
        }
    }
}

// ---------------- PTX helpers ----------------
__device__ __forceinline__ void cp16(uint32_t s, const void* g) {
    asm volatile("cp.async.cg.shared.global [%0], [%1], 16;\n" :: "r"(s), "l"(g));
}
__device__ __forceinline__ void cp_commit() { asm volatile("cp.async.commit_group;\n"); }
__device__ __forceinline__ void cp_wait0()  { asm volatile("cp.async.wait_group 0;\n"); }
__device__ __forceinline__ void cp_wait1()  { asm volatile("cp.async.wait_group 1;\n"); }
__device__ __forceinline__ void cp_wait2()  { asm volatile("cp.async.wait_group 2;\n"); }

__device__ __forceinline__ void fma2(unsigned long long& d,
                                     unsigned long long a, unsigned long long b) {
    asm("fma.rn.f32x2 %0, %1, %2, %0;" : "+l"(d) : "l"(a), "l"(b));
}

// ---------------- one GRU layer pass (this CTA's 8 features) --------------
// 48 virtual rows m = fam*24 + gate*8 + jj. Warp (q, rh): k-quarter q,
// family rh (rh=0: Wih rows dotted with x; rh=1: Whh rows dotted with h).
// Each warp has a private 3-stage cp.async pipeline; W is expanded to
// duplicated (w,w) pairs in smem (row stride 17 float2 => bank-spread)
// so FMA2's B operand is a single conflict-free LDS.64 broadcast.
__device__ __noinline__ void gru_phase(
    float* sm, uint32_t sb,
    const float* __restrict__ Axg, const float* __restrict__ Ahg,
    float* __restrict__ hnext,
    const float* __restrict__ Wi, const float* __restrict__ Wh,
    const float* __restrict__ bi, const float* __restrict__ bh,
    int j0)
{
    const int tid  = threadIdx.x;
    const int warp = tid >> 5, lane = tid & 31;
    const int q    = warp >> 1, rh = warp & 1;
    const int tb   = lane & 7,  tn = lane >> 3;

    const float* asrc = (rh ? Ahg : Axg) + (size_t)q * (256 * 64);

    // W source pointers: 3 chunks of 4 floats per lane per k-block
    const float* wsrc[3];
    #pragma unroll
    for (int i = 0; i < 3; ++i) {
        int c    = lane + 32 * i;        // 0..95
        int mrow = c >> 2;               // 0..23 (row within family)
        int wrow = (mrow >> 3) * Hn + j0 + (mrow & 7);
        wsrc[i] = (rh ? Wh : Wi) + (size_t)wrow * Hn + q * 256 + (c & 3) * 4;
    }

    uint32_t wb = sb + (uint32_t)warp * (WSZ * 4);

    auto load_blk = [&](int kb, int s) {
        uint32_t aso = wb + (uint32_t)s * 4096;          // A stage (1024 floats)
        const float* ga = asrc + kb * 1024;
        #pragma unroll
        for (int i = 0; i < 8; ++i) {
            int idx = lane + 32 * i;                     // 0..255
            cp16(aso + (uint32_t)idx * 16, ga + idx * 4);
        }
        uint32_t wso = wb + (uint32_t)(WR_O + s * 384) * 4;
        #pragma unroll
        for (int i = 0; i < 3; ++i) {
            int c = lane + 32 * i;
            cp16(wso + (uint32_t)c * 16, wsrc[i] + kb * 16);
        }
        cp_commit();
    };

    float* wraw_base = sm + warp * WSZ + WR_O;
    float2* dup      = (float2*)(sm + warp * WSZ + WD_O);

    auto expand_w = [&](int s) {
        const float4* raw = (const float4*)(wraw_base + s * 384);
        #pragma unroll
        for (int i = 0; i < 3; ++i) {
            int c = lane + 32 * i;
            int mrow = c >> 2, grp = c & 3;
            float4 v = raw[c];
            float2* d = dup + mrow * 17 + grp * 4;       // stride 17: bank-spread
            d[0] = make_float2(v.x, v.x);
            d[1] = make_float2(v.y, v.y);
            d[2] = make_float2(v.z, v.z);
            d[3] = make_float2(v.w, v.w);
        }
    };

    unsigned long long acc[6][4];
    #pragma unroll
    for (int ni = 0; ni < 6; ++ni)
        #pragma unroll
        for (int p = 0; p < 4; ++p) acc[ni][p] = 0ull;

    load_blk(0, 0);
    load_blk(1, 1);

    const float* paB = sm + warp * WSZ + tb * 4;
    const unsigned long long* pwB =
        (const unsigned long long*)dup + (size_t)tn * 6 * 17;

    #pragma unroll 1
    for (int kb = 0; kb < NKBQ; ++kb) {
        if (kb + 2 < NKBQ)      { load_blk(kb + 2, (kb + 2) % 3); cp_wait2(); }
        else if (kb + 1 < NKBQ) { cp_wait1(); }
        else                    { cp_wait0(); }
        __syncwarp();
        expand_w(kb % 3);
        __syncwarp();
        const float* pa = paB + (kb % 3) * 1024;
        #pragma unroll
        for (int k = 0; k < KCQ; ++k) {
            const float* rk = pa + k * 64;
            ulonglong2 A0 = *(const ulonglong2*)rk;          // batches 4tb..4tb+3
            ulonglong2 A1 = *(const ulonglong2*)(rk + 32);   // batches 32+4tb..
            #pragma unroll
            for (int ni = 0; ni < 6; ++ni) {
                unsigned long long ww = pwB[ni * 17 + k];
                fma2(acc[ni][0], A0.x, ww);
                fma2(acc[ni][1], A0.y, ww);
                fma2(acc[ni][2], A1.x, ww);
                fma2(acc[ni][3], A1.y, ww);
            }
        }
        __syncwarp();
    }

    // stage partials: sC[q][m_all][b]
    float* sc = sm + SCO + q * SCKT;
    #pragma unroll
    for (int ni = 0; ni < 6; ++ni) {
        int m = rh * 24 + tn * 6 + ni;
        float* row = sc + m * 66;
        *(unsigned long long*)(row + 4 * tb)          = acc[ni][0];
        *(unsigned long long*)(row + 4 * tb + 2)      = acc[ni][1];
        *(unsigned long long*)(row + 32 + 4 * tb)     = acc[ni][2];
        *(unsigned long long*)(row + 32 + 4 * tb + 2) = acc[ni][3];
    }
    __syncthreads();

    // GRU combine: 256 threads = (batch b, feature pair jp)
    {
        int b = tid & 63, jp = tid >> 6;
        #pragma unroll
        for (int u = 0; u < 2; ++u) {
            int jj = 2 * jp + u;
            float g[6];
            #pragma unroll
            for (int e = 0; e < 6; ++e) {
                int m = (e / 3) * 24 + (e % 3) * 8 + jj;
                const float* p = sm + SCO + m * 66 + b;
                g[e] = (p[0] + p[SCKT]) + (p[2 * SCKT] + p[3 * SCKT]);
            }
            int j = j0 + jj;
            float ir  = g[0] + bi[j];
            float iz  = g[1] + bi[Hn + j];
            float inn = g[2] + bi[2 * Hn + j];
            float hr  = g[3] + bh[j];
            float hz  = g[4] + bh[Hn + j];
            float hnn = g[5] + bh[2 * Hn + j];
            float hv = __ldcg(Ahg + (size_t)j * 64 + b);
            float r = 1.f / (1.f + __expf(-(ir + hr)));
            float z = 1.f / (1.f + __expf(-(iz + hz)));
            float n = tanhf(inn + r * hnn);
            float hc = (1.f - z) * n + z * hv;
            __stcg(hnext + (size_t)j * 64 + b, 0.1f * hv + 0.9f * hc);
        }
    }
}

// ---------------- output projection (h1 is [j][b]) ------------------------
__device__ __noinline__ void proj_step(
    const float* __restrict__ h1, const float* __restrict__ Wout,
    const float* __restrict__ bout, float* __restrict__ out,
    int r0, int t)
{
    int b = threadIdx.x & 63, rp = threadIdx.x >> 6;   // 4 row-pairs
    int r = r0 + 2 * rp;
    float a0 = bout[r], a1 = bout[r + 1];
    const float* w0 = Wout + (size_t)r * Hn;
    const float* w1 = w0 + Hn;
    #pragma unroll 8
    for (int j = 0; j < Hn; ++j) {
        float hv = __ldcg(h1 + (size_t)j * 64 + b);
        a0 += hv * __ldg(w0 + j);
        a1 += hv * __ldg(w1 + j);
    }
    size_t ob = (size_t)b * 80000 + (size_t)t * 2;
    out[ob + (size_t)(r >> 1) * 1000 + (r & 1)]             = a0;
    out[ob + (size_t)((r + 1) >> 1) * 1000 + ((r + 1) & 1)] = a1;
}

// ---------------- persistent kernel ---------------------------------------
__global__ void __launch_bounds__(256, 1) k_persistent(
    const float* __restrict__ Wih, const float* __restrict__ Whh,
    const float* __restrict__ bih, const float* __restrict__ bhh,
    const float* __restrict__ Wout, const float* __restrict__ bout,
    float* __restrict__ out)
{
    extern __shared__ float sm[];
    uint32_t sb = (uint32_t)__cvta_generic_to_shared(sm);
    int cta = blockIdx.x;

    if (cta < NGEMM) {
        int j0 = cta * 8;
        const float* Wi1 = Wih + (size_t)3 * Hn * Hn;
        const float* Wh1 = Whh + (size_t)3 * Hn * Hn;
        for (int t = 0; t < Tn; ++t) {
            int p = t & 1;
            gru_phase(sm, sb, g_Xt + (size_t)t * BHn, g_h0[p], g_h0[p ^ 1],
                      Wih, Whh, bih, bhh, j0);
            grid_bar();
            gru_phase(sm, sb, g_h0[p ^ 1], g_h1[p], g_h1[p ^ 1],
                      Wi1, Wh1, bih + 3 * Hn, bhh + 3 * Hn, j0);
            grid_bar();
        }
    } else {
        int r0 = (cta - NGEMM) * 8;
        for (int t = 0; t < Tn; ++t) {
            if (t > 0) proj_step(g_h1[t & 1], Wout, bout, out, r0, t - 1);
            grid_bar();
            grid_bar();
        }
        proj_step(g_h1[((Tn - 1) & 1) ^ 1], Wout, bout, out, r0, Tn - 1);
    }
}

// ---------------- launch ---------------------------------------------------
extern "C" void kernel_launch(void* const* d_in, const int* in_sizes, int n_in,
                              void* d_out, int out_size)
{
    const float* res  = (const float*)d_in[0];
    const float* Wih  = (const float*)d_in[1];
    const float* Whh  = (const float*)d_in[2];
    const float* bih  = (const float*)d_in[3];
    const float* bhh  = (const float*)d_in[4];
    const float* Wout = (const float*)d_in[5];
    const float* bout = (const float*)d_in[6];
    float* out = (float*)d_out;
    (void)in_sizes; (void)n_in; (void)out_size;

    cudaFuncSetAttribute(k_persistent,
                         cudaFuncAttributeMaxDynamicSharedMemorySize, SMB);

    void* h0p = nullptr; void* h1p = nullptr;
    cudaGetSymbolAddress(&h0p, g_h0);
    cudaGetSymbolAddress(&h1p, g_h1);
    cudaMemsetAsync(h0p, 0, sizeof(float) * 2 * BHn, 0);
    cudaMemsetAsync(h1p, 0, sizeof(float) * 2 * BHn, 0);

    dim3 tb(32, 8), tg((Tn + 31) / 32, Hn);
    k_transpose<<<tg, tb>>>(res);

    k_persistent<<<NCTA, 256, SMB>>>(Wih, Whh, bih, bhh, Wout, bout, out);
}